// round 14
// baseline (speedup 1.0000x reference)
#include <cuda_runtime.h>
#include <cuda_fp16.h>
#include <cstdint>

// ============================================================
// Detect head via mma.sync, fp16 operands / fp32 accum.
// R14: persistent balanced scheduler (296 CTAs, ~20 chunk-units
// each) + cross-tile register prefetch (v,u) so each tile's
// chunk-0 X latency hides under the previous tile's MMA+epilogue.
// K-chunk=64, double-buffered dynamic smem, cp.async W.
// ============================================================

#define TPB 256
#define SROW 88
#define NCTA 296

// dynamic smem layout
#define XS0 0            // 64 k-rows x 256B (swizzled fp16) = 16384
#define XS1 16384
#define WS0 32768        // 96 n-rows x 144B = 13824
#define WS1 46592
#define SMEM_BYTES 60416

__device__ __forceinline__ uint32_t smem_u32(const void* p) {
    uint32_t a;
    asm("{ .reg .u64 t; cvta.to.shared.u64 t, %1; cvt.u32.u64 %0, t; }" : "=r"(a) : "l"(p));
    return a;
}

#define LDMX4T(r, addr) \
    asm volatile("ldmatrix.sync.aligned.m8n8.x4.trans.shared.b16 {%0,%1,%2,%3}, [%4];" \
        : "=r"((r)[0]), "=r"((r)[1]), "=r"((r)[2]), "=r"((r)[3]) : "r"(addr))

#define LDMX4(r, addr) \
    asm volatile("ldmatrix.sync.aligned.m8n8.x4.shared.b16 {%0,%1,%2,%3}, [%4];" \
        : "=r"((r)[0]), "=r"((r)[1]), "=r"((r)[2]), "=r"((r)[3]) : "r"(addr))

#define MMA16816(d, a, b0, b1) \
    asm volatile("mma.sync.aligned.m16n8k16.row.col.f32.f16.f16.f32 " \
        "{%0,%1,%2,%3}, {%4,%5,%6,%7}, {%8,%9}, {%0,%1,%2,%3};" \
        : "+f"((d)[0]), "+f"((d)[1]), "+f"((d)[2]), "+f"((d)[3]) \
        : "r"((a)[0]), "r"((a)[1]), "r"((a)[2]), "r"((a)[3]), "r"(b0), "r"(b1))

#define CP_ASYNC16(dst, src) \
    asm volatile("cp.async.ca.shared.global [%0], [%1], 16;" :: "r"(dst), "l"(src))
#define CP_COMMIT() asm volatile("cp.async.commit_group;" ::: "memory")
#define CP_WAIT0()  asm volatile("cp.async.wait_group 0;" ::: "memory")

// 28 chunks of 64 channels: [96 n][64 k] fp16 each (12 KB)
__device__ __align__(16) __half g_Wh[28 * 96 * 64];

__global__ void prep_W(const float* __restrict__ W0, const float* __restrict__ W1,
                       const float* __restrict__ W2)
{
    int idx = blockIdx.x * blockDim.x + threadIdx.x;
    if (idx >= 28 * 96 * 64) return;
    int ch = idx / 6144, rem = idx - ch * 6144;
    int n = rem >> 6, k = rem & 63;
    const float* W; int C, cb;
    if (ch < 4)       { W = W0; C = 256;  cb = ch * 64; }
    else if (ch < 12) { W = W1; C = 512;  cb = (ch - 4) * 64; }
    else              { W = W2; C = 1024; cb = (ch - 12) * 64; }
    float v = (n < 85) ? W[(size_t)n * C + cb + k] : 0.0f;
    g_Wh[idx] = __float2half(v);
}

__device__ __forceinline__ uint32_t h2u(__half2 h) {
    return *reinterpret_cast<uint32_t*>(&h);
}

// ---- schedule: 296 CTAs, balanced ~20 chunk-units each ----
__device__ __forceinline__ int tile_count(int c) {
    return (c < 64) ? 2 : (c < 272) ? 4 : (((c - 272) < 16) ? 5 : 4);
}
__device__ __forceinline__ void tile_of(int c, int i, int& lvl, int& b, int& m0) {
    if (c < 64) {
        if (i == 0) { lvl = 2; b = c >> 2; m0 = (c & 3) * 128; return; }
        int t0 = c;           lvl = 0; b = t0 / 50; m0 = (t0 % 50) * 128; return;
    } else if (c < 272) {
        int t1 = c - 64;
        if (i == 0) { lvl = 1; b = t1 / 13; m0 = (t1 % 13) * 128; return; }
        int t0 = 64 + 3 * t1 + (i - 1);
        lvl = 0; b = t0 / 50; m0 = (t0 % 50) * 128; return;
    }
    int cp = c - 272;
    int t0 = (cp < 16) ? (688 + 5 * cp + i) : (768 + 4 * (cp - 16) + i);
    lvl = 0; b = t0 / 50; m0 = (t0 % 50) * 128;
}
__device__ __forceinline__ int NHW_of(int l) { return l == 0 ? 6400 : (l == 1 ? 1600 : 400); }
__device__ __forceinline__ int C_of(int l)   { return 256 << l; }
__device__ __forceinline__ int off_of(int l) { return l == 0 ? 0 : (l == 1 ? 6400 : 8000); }
__device__ __forceinline__ int chb_of(int l) { return l == 0 ? 0 : (l == 1 ? 4 : 12); }

// runtime X half-wave loader: rows rbase+k0+8it, 64 positions from m0
__device__ __forceinline__
void loadX_rt(const float* __restrict__ Xb, int NHW, int m0, int rbase,
              int k0, int m4, float4 (&v)[4])
{
    if (m0 + 128 <= NHW) {
        const float* p = Xb + (size_t)(rbase + k0) * NHW + m0 + m4 * 4;
#pragma unroll
        for (int it = 0; it < 4; it++)
            v[it] = *reinterpret_cast<const float4*>(p + (size_t)(8 * it) * NHW);
    } else {
        int lim = NHW - 1 - m0; if (lim < 0) lim = 0;
#pragma unroll
        for (int it = 0; it < 4; it++) {
            const float* src = Xb + (size_t)(rbase + k0 + 8 * it) * NHW + m0;
            v[it].x = src[min(m4 * 4 + 0, lim)];
            v[it].y = src[min(m4 * 4 + 1, lim)];
            v[it].z = src[min(m4 * 4 + 2, lim)];
            v[it].w = src[min(m4 * 4 + 3, lim)];
        }
    }
}

__global__ __launch_bounds__(TPB, 2)
void detect_tc(const float* __restrict__ x0, const float* __restrict__ x1,
               const float* __restrict__ x2,
               const float* __restrict__ b0, const float* __restrict__ b1,
               const float* __restrict__ b2, float* __restrict__ out)
{
    extern __shared__ __align__(1024) char sm[];
    const uint32_t sb = smem_u32(sm);
    const int c = blockIdx.x;
    const int nt = tile_count(c);

    const int tid = threadIdx.x;
    const int lane = tid & 31, wid = tid >> 5;
    const int wm = wid >> 1, wn = wid & 1;

    // ---- hoisted per-thread addressing ----
    const int k0 = tid >> 5, m4q = tid & 31;
    const uint32_t offX0 = (uint32_t)(k0 * 256 + ((m4q * 8) ^ ((k0 & 7) << 4)));
    uint32_t aoffA[2];
    {
        const int mat = lane >> 3, r = lane & 7;
#pragma unroll
        for (int mf = 0; mf < 2; mf++) {
            int kb = ((mat >> 1) << 3) + r;
            int mb = (wm * 32 + mf * 16 + ((mat & 1) << 3)) * 2;
            aoffA[mf] = (uint32_t)(kb * 256 + (mb ^ (r << 4)));
        }
    }
    uint32_t relB[3];
    {
        const int grp = lane >> 3, rsel = lane & 7;
#pragma unroll
        for (int j = 0; j < 3; j++)
            relB[j] = (uint32_t)((wn * 48 + (j * 2 + (grp >> 1)) * 8 + rsel) * 144
                                 + (grp & 1) * 16);
    }
    const int g = lane >> 2, c0 = lane & 3;

    auto xptr = [&](int l) { return l == 0 ? x0 : (l == 1 ? x1 : x2); };
    auto bptr = [&](int l) { return l == 0 ? b0 : (l == 1 ? b1 : b2); };

    auto convertX = [&](const float4 (&vv)[4], uint32_t xsOff, int half) {
        uint32_t base = xsOff + offX0 + (uint32_t)half * 8192;
#pragma unroll
        for (int it = 0; it < 4; it++) {
            __half2 h0 = __floats2half2_rn(vv[it].x, vv[it].y);
            __half2 h1 = __floats2half2_rn(vv[it].z, vv[it].w);
            *reinterpret_cast<uint2*>(sm + base + it * 2048) = make_uint2(h2u(h0), h2u(h1));
        }
    };
    auto stageW = [&](int chAbs, uint32_t wsOff) {
        const uint4* wsrc = reinterpret_cast<const uint4*>(&g_Wh[(size_t)chAbs * 6144]);
#pragma unroll
        for (int it = 0; it < 3; it++) {
            uint32_t u = tid + it * TPB;
            CP_ASYNC16(sb + wsOff + (u >> 3) * 144 + (u & 7) * 16, wsrc + u);
        }
        CP_COMMIT();
    };

    float acc[2][6][4];
    float4 v[4], u[4];

    // ---- first tile prefetch (only exposed fill in the whole CTA) ----
    {
        int lvl, b, m0; tile_of(c, 0, lvl, b, m0);
        const float* Xb = xptr(lvl) + (size_t)b * C_of(lvl) * NHW_of(lvl);
        loadX_rt(Xb, NHW_of(lvl), m0, 0, k0, m4q, v);
        loadX_rt(Xb, NHW_of(lvl), m0, 32, k0, m4q, u);
    }

    for (int i = 0; i < nt; i++) {
        int lvl, b, m0; tile_of(c, i, lvl, b, m0);
        const int NHW = NHW_of(lvl);
        const int NCH = C_of(lvl) >> 6;
        const int chBase = chb_of(lvl);
        const float* Xb = xptr(lvl) + (size_t)b * ((size_t)C_of(lvl) * NHW);
        const float* bias = bptr(lvl);
        const bool hasNext = (i + 1 < nt);

#pragma unroll
        for (int mf = 0; mf < 2; mf++)
#pragma unroll
            for (int f = 0; f < 6; f++)
#pragma unroll
                for (int e = 0; e < 4; e++) acc[mf][f][e] = 0.0f;

        // ---- tile prologue: both chunk-0 halves already in v,u ----
        stageW(chBase, WS0);
        convertX(v, XS0, 0);
        convertX(u, XS0, 1);
        loadX_rt(Xb, NHW, m0, 64, k0, m4q, v);   // chunk 1, half 0
        CP_WAIT0();
        __syncthreads();

        for (int chk = 0; chk < NCH; chk++) {
            const uint32_t xbase = sb + ((chk & 1) ? XS1 : XS0);
            const uint32_t wbase = sb + ((chk & 1) ? WS1 : WS0);
            const uint32_t xsNxt = (chk & 1) ? XS0 : XS1;
            const uint32_t wsNxt = (chk & 1) ? WS0 : WS1;
            const bool more = (chk + 1 < NCH);

            if (more) {
                stageW(chBase + chk + 1, wsNxt);
                convertX(v, xsNxt, 0);                          // (chk+1, half0)
                loadX_rt(Xb, NHW, m0, (chk + 1) * 64 + 32, k0, m4q, v);  // (chk+1, half1)
            }

            // ---- MMA first half ----
#pragma unroll
            for (int ks = 0; ks < 2; ks++) {
                uint32_t af[2][4];
                LDMX4T(af[0], xbase + aoffA[0] + ks * 4096);
                LDMX4T(af[1], xbase + aoffA[1] + ks * 4096);
#pragma unroll
                for (int j = 0; j < 3; j++) {
                    uint32_t br[4];
                    LDMX4(br, wbase + relB[j] + ks * 32);
                    MMA16816(acc[0][2 * j + 0], af[0], br[0], br[1]);
                    MMA16816(acc[1][2 * j + 0], af[1], br[0], br[1]);
                    MMA16816(acc[0][2 * j + 1], af[0], br[2], br[3]);
                    MMA16816(acc[1][2 * j + 1], af[1], br[2], br[3]);
                }
            }

            if (more) {
                convertX(v, xsNxt, 1);                          // (chk+1, half1)
                if (chk + 2 < NCH) {
                    loadX_rt(Xb, NHW, m0, (chk + 2) * 64, k0, m4q, v);
                } else if (hasNext) {
                    int nl, nb, nm; tile_of(c, i + 1, nl, nb, nm);
                    const float* nXb = xptr(nl) + (size_t)nb * ((size_t)C_of(nl) * NHW_of(nl));
                    loadX_rt(nXb, NHW_of(nl), nm, 0, k0, m4q, v);   // next tile (0, half0)
                }
            }

            // ---- MMA second half ----
#pragma unroll
            for (int ks = 2; ks < 4; ks++) {
                uint32_t af[2][4];
                LDMX4T(af[0], xbase + aoffA[0] + ks * 4096);
                LDMX4T(af[1], xbase + aoffA[1] + ks * 4096);
#pragma unroll
                for (int j = 0; j < 3; j++) {
                    uint32_t br[4];
                    LDMX4(br, wbase + relB[j] + ks * 32);
                    MMA16816(acc[0][2 * j + 0], af[0], br[0], br[1]);
                    MMA16816(acc[1][2 * j + 0], af[1], br[0], br[1]);
                    MMA16816(acc[0][2 * j + 1], af[0], br[2], br[3]);
                    MMA16816(acc[1][2 * j + 1], af[1], br[2], br[3]);
                }
            }

            CP_WAIT0();
            __syncthreads();
        }

        // ---- bias + sigmoid ----
#pragma unroll
        for (int f = 0; f < 6; f++) {
            int nb = wn * 48 + f * 8 + c0 * 2;
            float bv0 = (nb < 85) ? __ldg(&bias[nb]) : 0.0f;
            float bv1 = (nb + 1 < 85) ? __ldg(&bias[nb + 1]) : 0.0f;
#pragma unroll
            for (int mf = 0; mf < 2; mf++)
#pragma unroll
                for (int h = 0; h < 2; h++) {
                    float p0 = acc[mf][f][h * 2 + 0] + bv0;
                    float p1 = acc[mf][f][h * 2 + 1] + bv1;
                    acc[mf][f][h * 2 + 0] = __fdividef(1.0f, 1.0f + __expf(-p0));
                    acc[mf][f][h * 2 + 1] = __fdividef(1.0f, 1.0f + __expf(-p1));
                }
        }

        // ---- box decode (channels 0..3 live in wn==0, f==0, c0<2) ----
        if (wn == 0) {
            const int NX = 80 >> lvl;
            const float power = (float)(1 << lvl);
            const float strd  = (float)(8 << lvl);
#pragma unroll
            for (int mf = 0; mf < 2; mf++)
#pragma unroll
                for (int h = 0; h < 2; h++) {
                    float s0 = acc[mf][0][h * 2 + 0];
                    float s1 = acc[mf][0][h * 2 + 1];
                    float q0 = 4.0f * s0 * s0 * power;
                    float q1 = 4.0f * s1 * s1 * power;
                    float p0 = __shfl_xor_sync(0xffffffffu, q0, 1);
                    float p1 = __shfl_xor_sync(0xffffffffu, q1, 1);
                    float dx1 = (c0 == 0) ? q0 : p0;
                    float dy1 = (c0 == 0) ? q1 : p1;
                    float dx2 = (c0 == 0) ? p0 : q0;
                    float dy2 = (c0 == 0) ? p1 : q1;
                    int pos = m0 + wm * 32 + mf * 16 + h * 8 + g;
                    int iy = pos / NX, ix = pos - iy * NX;
                    float x1 = ((float)ix + 1.0f - dx1) * strd;
                    float y1 = ((float)iy + 1.0f - dy1) * strd;
                    float x2 = ((float)ix + dx2) * strd;
                    float y2 = ((float)iy + dy2) * strd;
                    if (c0 == 0) {
                        acc[mf][0][h * 2 + 0] = 0.5f * (x1 + x2);
                        acc[mf][0][h * 2 + 1] = 0.5f * (y1 + y2);
                    } else if (c0 == 1) {
                        acc[mf][0][h * 2 + 0] = x2 - x1;
                        acc[mf][0][h * 2 + 1] = y2 - y1;
                    }
                }
        }

        // ---- staged coalesced store: 2 waves of 64 positions ----
        float* S = reinterpret_cast<float*>(sm);
        const int lvlOff = off_of(lvl);
#pragma unroll
        for (int w = 0; w < 2; w++) {
            __syncthreads();
            if ((wm >> 1) == w) {
                int mbase = (wm & 1) * 32;
#pragma unroll
                for (int mf = 0; mf < 2; mf++)
#pragma unroll
                    for (int h = 0; h < 2; h++) {
                        int mrow = mbase + mf * 16 + h * 8 + g;
#pragma unroll
                        for (int f = 0; f < 6; f++) {
                            int n = wn * 48 + f * 8 + c0 * 2;
                            if (n + 1 < 85)
                                *reinterpret_cast<float2*>(&S[mrow * SROW + n]) =
                                    make_float2(acc[mf][f][h * 2], acc[mf][f][h * 2 + 1]);
                            else if (n < 85)
                                S[mrow * SROW + n] = acc[mf][f][h * 2];
                        }
                    }
            }
            __syncthreads();
            if (w == 1 && hasNext) {     // acc fully staged -> prefetch next (0, half1)
                int nl, nb, nm; tile_of(c, i + 1, nl, nb, nm);
                const float* nXb = xptr(nl) + (size_t)nb * ((size_t)C_of(nl) * NHW_of(nl));
                loadX_rt(nXb, NHW_of(nl), nm, 32, k0, m4q, u);
            }
            int valid = NHW - (m0 + w * 64);
            valid = valid < 0 ? 0 : (valid > 64 ? 64 : valid);
            float* ob = out + ((size_t)b * 8400 + lvlOff + m0 + w * 64) * 85;
#pragma unroll
            for (int r = 0; r < 8; r++) {
                int p = wid + r * 8;
                if (p < valid) {
                    const float* srow = &S[p * SROW];
                    float* orow = ob + (size_t)p * 85;
                    orow[lane] = srow[lane];
                    orow[lane + 32] = srow[lane + 32];
                    if (lane < 21) orow[lane + 64] = srow[lane + 64];
                }
            }
        }
        __syncthreads();   // S reads done before next tile's XS staging
    }
}

extern "C" void kernel_launch(void* const* d_in, const int* in_sizes, int n_in,
                              void* d_out, int out_size)
{
    const float* x0 = (const float*)d_in[0];
    const float* x1 = (const float*)d_in[1];
    const float* x2 = (const float*)d_in[2];
    const float* W0 = (const float*)d_in[3];
    const float* b0 = (const float*)d_in[4];
    const float* W1 = (const float*)d_in[5];
    const float* b1 = (const float*)d_in[6];
    const float* W2 = (const float*)d_in[7];
    const float* b2 = (const float*)d_in[8];
    float* out = (float*)d_out;

    cudaFuncSetAttribute(detect_tc, cudaFuncAttributeMaxDynamicSharedMemorySize,
                         SMEM_BYTES);
    prep_W<<<(28 * 96 * 64 + 255) / 256, 256>>>(W0, W1, W2);
    detect_tc<<<NCTA, TPB, SMEM_BYTES>>>(x0, x1, x2, b0, b1, b2, out);
}